// round 11
// baseline (speedup 1.0000x reference)
#include <cuda_runtime.h>

// FINAL — measured-optimal kernel, held unchanged (session answer).
// Output = 1.0f everywhere.
//
// Analytic reduction of the reference: the circuit is AngleEmbedding(RZ) +
// BasicEntanglerLayers(RZ + CNOT ring) applied to |0...0>. RZ gates are
// diagonal (pure phases on the single nonzero amplitude); CNOTs are basis
// permutations that all fix index 0 (control bit is 0 there). So the state
// remains the basis state |0...0> up to a global phase, probs is a delta at
// index 0, and <Z_i> = +1 for every wire — independent of inputs and weights.
//
// Constant fill of 2 MiB at the launch/ramp floor. Evidence from 11 benches:
// kernel dur 3.616-3.936us across the full swept design space (grid
// 64/128/512 x block 256/512 x 1/2/4/8 stores/thread); every HW resource
// <= 5.6% utilized; total dur_us jitters 4.5-6.9us independent of kernel dur
// (harness replay noise). Shape: single wave of 128 CTAs x 256 threads x
// 4 independent STG.128 per thread.

__global__ __launch_bounds__(256) void fill_ones_x4(float4* __restrict__ out) {
    const float4 ones = make_float4(1.0f, 1.0f, 1.0f, 1.0f);
    unsigned base = blockIdx.x * 1024u + threadIdx.x;
    out[base]        = ones;
    out[base + 256]  = ones;
    out[base + 512]  = ones;
    out[base + 768]  = ones;
}

// Generic fallback for sizes not divisible by 4096 floats.
__global__ __launch_bounds__(256) void fill_ones_generic(float* __restrict__ out, int n) {
    int i = blockIdx.x * 256 + threadIdx.x;
    for (; i < n; i += gridDim.x * 256) out[i] = 1.0f;
}

extern "C" void kernel_launch(void* const* d_in, const int* in_sizes, int n_in,
                              void* d_out, int out_size) {
    (void)d_in; (void)in_sizes; (void)n_in;
    float* out = (float*)d_out;

    // Fast path: out_size divisible by 256 threads * 4 float4 * 4 floats = 4096.
    if ((out_size & 4095) == 0 && out_size > 0) {
        int blocks = out_size >> 12;                 // 524288 -> 128 blocks
        fill_ones_x4<<<blocks, 256>>>((float4*)out);
    } else {
        int blocks = (out_size + 255) / 256;
        if (blocks > 1184) blocks = 1184;
        fill_ones_generic<<<blocks, 256>>>(out, out_size);
    }
}

// round 12
// speedup vs baseline: 1.1559x; 1.1559x over previous
#include <cuda_runtime.h>

// FINAL — measured-optimal kernel, held unchanged (session answer).
// Output = 1.0f everywhere.
//
// Analytic reduction of the reference: the circuit is AngleEmbedding(RZ) +
// BasicEntanglerLayers(RZ + CNOT ring) applied to |0...0>. RZ gates are
// diagonal (pure phases on the single nonzero amplitude); CNOTs are basis
// permutations that all fix index 0 (control bit is 0 there). So the state
// remains the basis state |0...0> up to a global phase, probs is a delta at
// index 0, and <Z_i> = +1 for every wire — independent of inputs and weights.
//
// Constant fill of 2 MiB at the launch/ramp floor. Evidence from 12 benches:
// kernel dur 3.616-3.936us across the full swept design space (grid
// 64/128/512 x block 256/512 x 1/2/4/8 stores/thread); every HW resource
// <= 5.6% utilized; total dur_us jitters 4.5-6.9us independent of kernel dur
// (harness replay noise). Shape: single wave of 128 CTAs x 256 threads x
// 4 independent STG.128 per thread. No remaining lever: 1 kernel node is the
// minimum capturable graph for a non-byte-uniform fill, STG.128 is the widest
// store, and the kernel is launch-overhead bound (stores ~0.2us of L2 traffic).

__global__ __launch_bounds__(256) void fill_ones_x4(float4* __restrict__ out) {
    const float4 ones = make_float4(1.0f, 1.0f, 1.0f, 1.0f);
    unsigned base = blockIdx.x * 1024u + threadIdx.x;
    out[base]        = ones;
    out[base + 256]  = ones;
    out[base + 512]  = ones;
    out[base + 768]  = ones;
}

// Generic fallback for sizes not divisible by 4096 floats.
__global__ __launch_bounds__(256) void fill_ones_generic(float* __restrict__ out, int n) {
    int i = blockIdx.x * 256 + threadIdx.x;
    for (; i < n; i += gridDim.x * 256) out[i] = 1.0f;
}

extern "C" void kernel_launch(void* const* d_in, const int* in_sizes, int n_in,
                              void* d_out, int out_size) {
    (void)d_in; (void)in_sizes; (void)n_in;
    float* out = (float*)d_out;

    // Fast path: out_size divisible by 256 threads * 4 float4 * 4 floats = 4096.
    if ((out_size & 4095) == 0 && out_size > 0) {
        int blocks = out_size >> 12;                 // 524288 -> 128 blocks
        fill_ones_x4<<<blocks, 256>>>((float4*)out);
    } else {
        int blocks = (out_size + 255) / 256;
        if (blocks > 1184) blocks = 1184;
        fill_ones_generic<<<blocks, 256>>>(out, out_size);
    }
}

// round 13
// speedup vs baseline: 1.4931x; 1.2917x over previous
#include <cuda_runtime.h>

// FINAL — measured-optimal kernel, held unchanged (session answer).
// Output = 1.0f everywhere.
//
// Analytic reduction of the reference: the circuit is AngleEmbedding(RZ) +
// BasicEntanglerLayers(RZ + CNOT ring) applied to |0...0>. RZ gates are
// diagonal (pure phases on the single nonzero amplitude); CNOTs are basis
// permutations that all fix index 0 (control bit is 0 there). So the state
// remains the basis state |0...0> up to a global phase, probs is a delta at
// index 0, and <Z_i> = +1 for every wire — independent of inputs and weights.
//
// Constant fill of 2 MiB at the launch/ramp floor. Evidence from 13 benches:
// kernel dur 3.616-3.936us across the full swept design space (grid
// 64/128/512 x block 256/512 x 1/2/4/8 stores/thread); every HW resource
// <= 5.6% utilized; total dur_us jitters 4.5-6.9us independent of kernel dur
// (harness replay noise). Shape: single wave of 128 CTAs x 256 threads x
// 4 independent STG.128 per thread. No remaining lever: 1 kernel node is the
// minimum capturable graph for a non-byte-uniform fill, STG.128 is the widest
// store, and the kernel is launch-overhead bound (stores ~0.2us of L2 traffic).

__global__ __launch_bounds__(256) void fill_ones_x4(float4* __restrict__ out) {
    const float4 ones = make_float4(1.0f, 1.0f, 1.0f, 1.0f);
    unsigned base = blockIdx.x * 1024u + threadIdx.x;
    out[base]        = ones;
    out[base + 256]  = ones;
    out[base + 512]  = ones;
    out[base + 768]  = ones;
}

// Generic fallback for sizes not divisible by 4096 floats.
__global__ __launch_bounds__(256) void fill_ones_generic(float* __restrict__ out, int n) {
    int i = blockIdx.x * 256 + threadIdx.x;
    for (; i < n; i += gridDim.x * 256) out[i] = 1.0f;
}

extern "C" void kernel_launch(void* const* d_in, const int* in_sizes, int n_in,
                              void* d_out, int out_size) {
    (void)d_in; (void)in_sizes; (void)n_in;
    float* out = (float*)d_out;

    // Fast path: out_size divisible by 256 threads * 4 float4 * 4 floats = 4096.
    if ((out_size & 4095) == 0 && out_size > 0) {
        int blocks = out_size >> 12;                 // 524288 -> 128 blocks
        fill_ones_x4<<<blocks, 256>>>((float4*)out);
    } else {
        int blocks = (out_size + 255) / 256;
        if (blocks > 1184) blocks = 1184;
        fill_ones_generic<<<blocks, 256>>>(out, out_size);
    }
}

// round 14
// speedup vs baseline: 1.5035x; 1.0070x over previous
#include <cuda_runtime.h>

// FINAL — measured-optimal kernel, held unchanged (session answer).
// Output = 1.0f everywhere.
//
// Analytic reduction of the reference: the circuit is AngleEmbedding(RZ) +
// BasicEntanglerLayers(RZ + CNOT ring) applied to |0...0>. RZ gates are
// diagonal (pure phases on the single nonzero amplitude); CNOTs are basis
// permutations that all fix index 0 (control bit is 0 there). So the state
// remains the basis state |0...0> up to a global phase, probs is a delta at
// index 0, and <Z_i> = +1 for every wire — independent of inputs and weights.
//
// Constant fill of 2 MiB at the launch/ramp floor. Evidence from 14 benches:
// kernel dur 3.36-3.94us on byte-identical binaries (noise-dominated); every
// HW resource <= 5.9% utilized; total dur_us jitters 4.5-6.9us independent of
// kernel dur (harness replay noise). Swept design space: grid 64/128/512 x
// block 256/512 x 1/2/4/8 stores/thread — plateau minimum at this shape
// (single wave of 128 CTAs x 256 threads x 4 independent STG.128). No
// remaining lever: 1 kernel node is the minimum capturable graph for a
// non-byte-uniform fill, STG.128 is the widest store, and the kernel is
// launch-overhead bound (stores are ~0.2us of L2 traffic).

__global__ __launch_bounds__(256) void fill_ones_x4(float4* __restrict__ out) {
    const float4 ones = make_float4(1.0f, 1.0f, 1.0f, 1.0f);
    unsigned base = blockIdx.x * 1024u + threadIdx.x;
    out[base]        = ones;
    out[base + 256]  = ones;
    out[base + 512]  = ones;
    out[base + 768]  = ones;
}

// Generic fallback for sizes not divisible by 4096 floats.
__global__ __launch_bounds__(256) void fill_ones_generic(float* __restrict__ out, int n) {
    int i = blockIdx.x * 256 + threadIdx.x;
    for (; i < n; i += gridDim.x * 256) out[i] = 1.0f;
}

extern "C" void kernel_launch(void* const* d_in, const int* in_sizes, int n_in,
                              void* d_out, int out_size) {
    (void)d_in; (void)in_sizes; (void)n_in;
    float* out = (float*)d_out;

    // Fast path: out_size divisible by 256 threads * 4 float4 * 4 floats = 4096.
    if ((out_size & 4095) == 0 && out_size > 0) {
        int blocks = out_size >> 12;                 // 524288 -> 128 blocks
        fill_ones_x4<<<blocks, 256>>>((float4*)out);
    } else {
        int blocks = (out_size + 255) / 256;
        if (blocks > 1184) blocks = 1184;
        fill_ones_generic<<<blocks, 256>>>(out, out_size);
    }
}